// round 6
// baseline (speedup 1.0000x reference)
#include <cuda_runtime.h>
#include <math.h>

#define S_LEN 128
#define B_SZ  64
#define I_SZ  256
#define H_SZ  512
#define O_SZ  256
#define NMAX  8
#define NBLK  64

typedef unsigned long long u64;

// ---------------- device scratch (static; allocation is forbidden) ----------------
__device__ __align__(16) float g_preT[S_LEN * H_SZ * B_SZ];   // [t][j][b]
__device__ __align__(16) float g_accsT[S_LEN * H_SZ * B_SZ];  // [t][j][b]
__device__ __align__(16) float g_hT[2 * H_SZ * B_SZ];         // ping-pong [buf][j][b]
__device__ __align__(16) float g_haltpart[2 * B_SZ * NBLK];   // [parity][b][blk]
__device__ unsigned g_arrive[NBLK];                           // per-block barrier flags

__device__ __forceinline__ void ffma2(u64 &d, u64 a, u64 b) {
    asm("fma.rn.f32x2 %0, %1, %2, %0;" : "+l"(d) : "l"(a), "l"(b));
}
__device__ __forceinline__ float lo32(u64 v) { return __uint_as_float((unsigned)(v & 0xffffffffu)); }
__device__ __forceinline__ float hi32(u64 v) { return __uint_as_float((unsigned)(v >> 32)); }
__device__ __forceinline__ u64 pack2(float x, float y) {
    return ((u64)__float_as_uint(y) << 32) | (u64)__float_as_uint(x);
}
__device__ __forceinline__ unsigned ld_acq(unsigned* p) {
    unsigned v;
    asm volatile("ld.acquire.gpu.u32 %0, [%1];" : "=r"(v) : "l"(p) : "memory");
    return v;
}
__device__ __forceinline__ void st_rel(unsigned* p, unsigned v) {
    asm volatile("st.release.gpu.u32 [%0], %1;" :: "l"(p), "r"(v) : "memory");
}

// distributed-flag grid barrier: each block releases its own slot with a
// monotonic step id; 64 threads each acquire-spin on one slot. Acquire on
// every flag + __syncthreads gives all threads cumulative visibility of all
// blocks' pre-barrier global writes. Bounded spin backoff after 64 polls.
__device__ __forceinline__ void flag_barrier(unsigned step, int blk, int tid) {
    __syncthreads();
    if (tid == 0) st_rel(&g_arrive[blk], step);
    if (tid < NBLK) {
        int polls = 0;
        while (ld_acq(&g_arrive[tid]) < step) {
            if (++polls > 64) __nanosleep(32);
        }
    }
    __syncthreads();
}

// ---------------- kernel 1: pre-projection GEMM ----------------
// g_preT[t][j][b] = b_ih[j]+b_hh[j] + sum_i x[t][b][i]*W_ih[j][1+i]
__global__ void __launch_bounds__(256) pre_gemm(const float* __restrict__ x,
                                                const float* __restrict__ W_ih,
                                                const float* __restrict__ b_ih,
                                                const float* __restrict__ b_hh) {
    __shared__ float Xs[64 * 65];   // [b][k]
    __shared__ float Ws[64 * 65];   // [j][k]
    const int t = blockIdx.y, jt = blockIdx.x;
    const int tid = threadIdx.x;
    const int ty = tid >> 4, tx = tid & 15;
    float acc[4][4] = {};
    for (int kc = 0; kc < 4; ++kc) {
        __syncthreads();
        for (int i = tid; i < 4096; i += 256) {
            int r = i >> 6, kk = i & 63;
            Xs[r * 65 + kk] = x[(t * 64 + r) * 256 + kc * 64 + kk];
            Ws[r * 65 + kk] = W_ih[(jt * 64 + r) * 257 + 1 + kc * 64 + kk];
        }
        __syncthreads();
        #pragma unroll 8
        for (int kk = 0; kk < 64; ++kk) {
            float wv[4], xv[4];
            #pragma unroll
            for (int a = 0; a < 4; ++a) wv[a] = Ws[(ty * 4 + a) * 65 + kk];
            #pragma unroll
            for (int c = 0; c < 4; ++c) xv[c] = Xs[(tx * 4 + c) * 65 + kk];
            #pragma unroll
            for (int a = 0; a < 4; ++a)
                #pragma unroll
                for (int c = 0; c < 4; ++c)
                    acc[a][c] = fmaf(wv[a], xv[c], acc[a][c]);
        }
    }
    #pragma unroll
    for (int a = 0; a < 4; ++a) {
        int j = jt * 64 + ty * 4 + a;
        float bias = b_ih[j] + b_hh[j];
        #pragma unroll
        for (int c = 0; c < 4; ++c) {
            int b = tx * 4 + c;
            g_preT[(t * 512 + j) * 64 + b] = acc[a][c] + bias;
        }
    }
}

// ---------------- init: transpose s[1,B,H] -> g_hT[0][j][b]; reset flags ----------------
__global__ void init_h(const float* __restrict__ s) {
    if (threadIdx.x == 0) g_arrive[blockIdx.x] = 0u;   // self-heal barrier state each launch
    int b = blockIdx.x;
    int j = threadIdx.x;
    g_hT[j * 64 + b] = s[b * 512 + j];
}

// ---------------- kernel 2: persistent ACT recurrence ----------------
__global__ void __launch_bounds__(256, 1) rnn_act(const float* __restrict__ W_hh,
                                                  const float* __restrict__ W_ih,
                                                  const float* __restrict__ W_halt,
                                                  const float* __restrict__ b_halt,
                                                  float* __restrict__ pond_out) {
    __shared__ __align__(16) u64   sh_W2[4096];      // [k=512][j=8] dup-pairs (32 KB)
    __shared__ __align__(16) u64   sh_part[1024];    // [grp=4][j=8][lane=32]   (8 KB)
    __shared__ float sh_hn[512];                     // [j=8][b=64]
    __shared__ float sh_accs[512];                   // [j=8][b=64]
    __shared__ float sh_cum[64];
    __shared__ float sh_w[64];
    __shared__ float sh_pond[64];
    __shared__ int   sh_halted[64];
    __shared__ float sh_whalt[8];
    __shared__ float sh_wih0[8];
    __shared__ float sh_bhalt;

    const int blk  = blockIdx.x;
    const int tid  = threadIdx.x;
    const int warp = tid >> 5, lane = tid & 31;

    // one-time: W_hh slice -> SMEM as duplicated f32x2 pairs, layout [k][j]
    for (int i = tid; i < 8 * 512; i += 256) {
        int j = i >> 9, k = i & 511;
        unsigned wb = __float_as_uint(W_hh[(blk * 8 + j) * 512 + k]);
        sh_W2[k * 8 + j] = ((u64)wb << 32) | (u64)wb;
    }
    if (tid < 8) {
        sh_whalt[tid] = W_halt[blk * 8 + tid];
        sh_wih0[tid]  = W_ih[(blk * 8 + tid) * 257];   // flag column W_ih[:,0]
    }
    if (tid == 0) sh_bhalt = b_halt[0];
    __syncthreads();

    unsigned bstep = 0;
    int rd = 0;
    for (int t = 0; t < S_LEN; ++t) {
        if (tid < 64) { sh_cum[tid] = 0.f; sh_pond[tid] = 0.f; sh_halted[tid] = 0; }
        for (int i = tid; i < 512; i += 256) sh_accs[i] = 0.f;
        __syncthreads();

        for (int n = 0; n < NMAX; ++n) {
            const int par = n & 1;
            // ---- phase A1: recurrent GEMM, K split across 8 warps ----
            u64 acc2[8] = {0ull,0ull,0ull,0ull,0ull,0ull,0ull,0ull};
            {
                const u64* hp = (const u64*)(g_hT + (rd << 15)) + (warp << 11) + lane;
                const ulonglong2* wp = (const ulonglong2*)(sh_W2 + ((warp << 6) << 3));
                #pragma unroll 4
                for (int kk = 0; kk < 64; ++kk) {
                    u64 h2 = __ldcg(hp + (kk << 5));
                    ulonglong2 w01 = wp[kk*4+0], w23 = wp[kk*4+1];
                    ulonglong2 w45 = wp[kk*4+2], w67 = wp[kk*4+3];
                    ffma2(acc2[0], h2, w01.x); ffma2(acc2[1], h2, w01.y);
                    ffma2(acc2[2], h2, w23.x); ffma2(acc2[3], h2, w23.y);
                    ffma2(acc2[4], h2, w45.x); ffma2(acc2[5], h2, w45.y);
                    ffma2(acc2[6], h2, w67.x); ffma2(acc2[7], h2, w67.y);
                }
            }
            if (warp < 4) {
                u64* pp = sh_part + (warp << 8) + lane;
                #pragma unroll
                for (int j = 0; j < 8; ++j) pp[j * 32] = acc2[j];
            }
            __syncthreads();
            if (warp >= 4) {   // fold high-warp partials into low-warp slots (fixed order)
                u64* pp = sh_part + ((warp - 4) << 8) + lane;
                #pragma unroll
                for (int j = 0; j < 8; ++j) {
                    u64 v = pp[j * 32];
                    pp[j * 32] = pack2(lo32(v) + lo32(acc2[j]), hi32(v) + hi32(acc2[j]));
                }
            }
            __syncthreads();
            // ---- phase A2: reduce 4 groups, bias+flag, tanh; publish h_new ----
            {
                const int j = tid >> 5, b0 = (tid & 31) * 2;
                float sx = 0.f, sy = 0.f;
                #pragma unroll
                for (int g = 0; g < 4; ++g) {
                    u64 v = sh_part[((g << 3) + j) * 32 + (tid & 31)];
                    sx += lo32(v); sy += hi32(v);
                }
                const int gj = blk * 8 + j;
                const float2 pre2 = *(const float2*)(g_preT + ((t * 512 + gj) << 6) + b0);
                float ax = sx + pre2.x, ay = sy + pre2.y;
                if (n == 0) { float f = sh_wih0[j]; ax += f; ay += f; }
                float hx = tanhf(ax), hy = tanhf(ay);
                sh_hn[(j << 6) + b0]     = hx;
                sh_hn[(j << 6) + b0 + 1] = hy;
                *(float2*)(g_hT + ((rd ^ 1) << 15) + (gj << 6) + b0) = make_float2(hx, hy);
            }
            __syncthreads();
            // ---- phase A3: halt-dot partial -> g_haltpart[par][b][blk] (fixed j order) ----
            if (tid < 64) {
                float s = 0.f;
                #pragma unroll
                for (int j = 0; j < 8; ++j) s += sh_whalt[j] * sh_hn[(j << 6) + tid];
                g_haltpart[(par << 12) + (tid << 6) + blk] = s;
            }
            ++bstep;
            flag_barrier(bstep, blk, tid);
            // ---- phase B: all blocks compute identical halting decisions ----
            if (tid < 64) {
                const float4* hp4 = (const float4*)(g_haltpart + (par << 12) + (tid << 6));
                float acc = 0.f;
                #pragma unroll
                for (int q = 0; q < 16; ++q) {
                    float4 v = __ldcg(hp4 + q);
                    acc += v.x; acc += v.y; acc += v.z; acc += v.w;
                }
                float p = 1.f / (1.f + expf(-(acc + sh_bhalt)));
                int hl = sh_halted[tid];
                if (hl) p = 0.f;
                float cum = sh_cum[tid];
                int is_h = (!hl) && (((cum + p) >= (1.0f - 0.01f)) || (n == NMAX - 1));
                sh_w[tid] = is_h ? (1.f - cum) : p;
                if (is_h) sh_pond[tid] = (1.f - cum) + (float)(n + 1);
                sh_cum[tid] = cum + p;
                sh_halted[tid] = hl | is_h;
            }
            __syncthreads();
            {
                const int j = tid >> 5, b0 = (tid & 31) * 2;
                sh_accs[(j << 6) + b0]     += sh_w[b0]     * sh_hn[(j << 6) + b0];
                sh_accs[(j << 6) + b0 + 1] += sh_w[b0 + 1] * sh_hn[(j << 6) + b0 + 1];
            }
            rd ^= 1;
            int allh = __syncthreads_and(tid < 64 ? sh_halted[tid] : 1);
            if (allh) break;
        }
        // ---- end of timestep: carry acc_s as next h; persist acc_s; write pond ----
        {
            const int j = tid >> 5, b0 = (tid & 31) * 2;
            const int gj = blk * 8 + j;
            float2 v = make_float2(sh_accs[(j << 6) + b0], sh_accs[(j << 6) + b0 + 1]);
            *(float2*)(g_hT + (rd << 15) + (gj << 6) + b0) = v;
            *(float2*)(g_accsT + ((t * 512 + gj) << 6) + b0) = v;
        }
        if (blk == 0 && tid < 64) pond_out[t * 64 + tid] = sh_pond[tid];
        ++bstep;
        flag_barrier(bstep, blk, tid);
    }
}

// ---------------- kernel 3: output GEMM ----------------
// out[t][b][o] = b_out[o] + sum_j g_accsT[t][j][b] * W_out[o][j]
__global__ void __launch_bounds__(256) out_gemm(const float* __restrict__ W_out,
                                                const float* __restrict__ b_out,
                                                float* __restrict__ out) {
    __shared__ float As[64 * 65];   // [k][b]
    __shared__ float Ws[64 * 65];   // [o][k]
    const int t = blockIdx.y, ot = blockIdx.x;
    const int tid = threadIdx.x;
    const int ty = tid >> 4, tx = tid & 15;
    float acc[4][4] = {};
    for (int kc = 0; kc < 8; ++kc) {
        __syncthreads();
        for (int i = tid; i < 4096; i += 256) {
            int r = i >> 6, c = i & 63;
            As[r * 65 + c] = g_accsT[(t * 512 + kc * 64 + r) * 64 + c];   // r=k, c=b
            Ws[r * 65 + c] = W_out[(ot * 64 + r) * 512 + kc * 64 + c];    // r=o, c=k
        }
        __syncthreads();
        #pragma unroll 8
        for (int kk = 0; kk < 64; ++kk) {
            float wv[4], xv[4];
            #pragma unroll
            for (int a = 0; a < 4; ++a) wv[a] = Ws[(ty * 4 + a) * 65 + kk];
            #pragma unroll
            for (int c = 0; c < 4; ++c) xv[c] = As[kk * 65 + tx * 4 + c];
            #pragma unroll
            for (int a = 0; a < 4; ++a)
                #pragma unroll
                for (int c = 0; c < 4; ++c)
                    acc[a][c] = fmaf(wv[a], xv[c], acc[a][c]);
        }
    }
    #pragma unroll
    for (int a = 0; a < 4; ++a) {
        int o = ot * 64 + ty * 4 + a;
        float bias = b_out[o];
        #pragma unroll
        for (int c = 0; c < 4; ++c) {
            int b = tx * 4 + c;
            out[(t * 64 + b) * 256 + o] = acc[a][c] + bias;
        }
    }
}

extern "C" void kernel_launch(void* const* d_in, const int* in_sizes, int n_in,
                              void* d_out, int out_size) {
    const float* x      = (const float*)d_in[0];
    const float* s      = (const float*)d_in[1];
    const float* W_ih   = (const float*)d_in[2];
    const float* b_ih   = (const float*)d_in[3];
    const float* W_hh   = (const float*)d_in[4];
    const float* b_hh   = (const float*)d_in[5];
    const float* W_out  = (const float*)d_in[6];
    const float* b_out  = (const float*)d_in[7];
    const float* W_halt = (const float*)d_in[8];
    const float* b_halt = (const float*)d_in[9];
    float* out  = (float*)d_out;                       // outputs [S,B,O]
    float* pond = out + S_LEN * B_SZ * O_SZ;           // ponder  [S,B]

    dim3 preg(8, S_LEN);
    pre_gemm<<<preg, 256>>>(x, W_ih, b_ih, b_hh);
    init_h<<<B_SZ, H_SZ>>>(s);
    rnn_act<<<NBLK, 256>>>(W_hh, W_ih, W_halt, b_halt, pond);
    dim3 outg(4, S_LEN);
    out_gemm<<<outg, 256>>>(W_out, b_out, out);
}

// round 8
// speedup vs baseline: 1.7170x; 1.7170x over previous
#include <cuda_runtime.h>
#include <math.h>

#define S_LEN 128
#define B_SZ  64
#define H_SZ  512
#define O_SZ  256
#define NMAX  8
#define NBLK  64

typedef unsigned long long u64;

// ---------------- device scratch (static; allocation is forbidden) ----------------
__device__ __align__(16) float g_preT[S_LEN * H_SZ * B_SZ];   // [t][j][b]
__device__ __align__(16) float g_accsT[S_LEN * H_SZ * B_SZ];  // [t][j][b]
__device__ __align__(16) float g_hbuf[3 * H_SZ * B_SZ];       // triple-buffer [buf][k][b]
__device__ __align__(16) float g_haltv[3 * NBLK * B_SZ];      // [buf][blk][b]
__device__ unsigned g_flag[NBLK * 32];                        // per-block flag, 128B stride

__device__ __forceinline__ void ffma2(u64 &d, u64 a, u64 b) {
    asm("fma.rn.f32x2 %0, %1, %2, %0;" : "+l"(d) : "l"(a), "l"(b));
}
__device__ __forceinline__ float lo32(u64 v) { return __uint_as_float((unsigned)(v & 0xffffffffu)); }
__device__ __forceinline__ float hi32(u64 v) { return __uint_as_float((unsigned)(v >> 32)); }
__device__ __forceinline__ u64 pack2(float x, float y) {
    return ((u64)__float_as_uint(y) << 32) | (u64)__float_as_uint(x);
}
__device__ __forceinline__ unsigned ld_acq(unsigned* p) {
    unsigned v;
    asm volatile("ld.acquire.gpu.u32 %0, [%1];" : "=r"(v) : "l"(p) : "memory");
    return v;
}
__device__ __forceinline__ void st_rel(unsigned* p, unsigned v) {
    asm volatile("st.release.gpu.u32 [%0], %1;" :: "l"(p), "r"(v) : "memory");
}

// ---------------- kernel 1: pre-projection GEMM ----------------
__global__ void __launch_bounds__(256) pre_gemm(const float* __restrict__ x,
                                                const float* __restrict__ W_ih,
                                                const float* __restrict__ b_ih,
                                                const float* __restrict__ b_hh) {
    __shared__ float Xs[64 * 65];
    __shared__ float Ws[64 * 65];
    const int t = blockIdx.y, jt = blockIdx.x;
    const int tid = threadIdx.x;
    const int ty = tid >> 4, tx = tid & 15;
    float acc[4][4] = {};
    for (int kc = 0; kc < 4; ++kc) {
        __syncthreads();
        for (int i = tid; i < 4096; i += 256) {
            int r = i >> 6, kk = i & 63;
            Xs[r * 65 + kk] = x[(t * 64 + r) * 256 + kc * 64 + kk];
            Ws[r * 65 + kk] = W_ih[(jt * 64 + r) * 257 + 1 + kc * 64 + kk];
        }
        __syncthreads();
        #pragma unroll 8
        for (int kk = 0; kk < 64; ++kk) {
            float wv[4], xv[4];
            #pragma unroll
            for (int a = 0; a < 4; ++a) wv[a] = Ws[(ty * 4 + a) * 65 + kk];
            #pragma unroll
            for (int c = 0; c < 4; ++c) xv[c] = Xs[(tx * 4 + c) * 65 + kk];
            #pragma unroll
            for (int a = 0; a < 4; ++a)
                #pragma unroll
                for (int c = 0; c < 4; ++c)
                    acc[a][c] = fmaf(wv[a], xv[c], acc[a][c]);
        }
    }
    #pragma unroll
    for (int a = 0; a < 4; ++a) {
        int j = jt * 64 + ty * 4 + a;
        float bias = b_ih[j] + b_hh[j];
        #pragma unroll
        for (int c = 0; c < 4; ++c) {
            int b = tx * 4 + c;
            g_preT[(t * 512 + j) * 64 + b] = acc[a][c] + bias;
        }
    }
}

// ---------------- init: s -> buf0 [k][b]; reset flags (self-heal every launch) ----------------
__global__ void init_h(const float* __restrict__ s) {
    if (threadIdx.x == 0) g_flag[blockIdx.x * 32] = 0u;
    int b = blockIdx.x;
    int j = threadIdx.x;
    g_hbuf[j * 64 + b] = s[b * 512 + j];
}

// ---------------- kernel 2: persistent ACT recurrence (dataflow-flag pipeline) ----------------
// Per sequential step: consume flag-protected h + halt vectors from step m,
// do the recurrent GEMM, finalize the (lagged) halting decision for ponder
// step q = n-1, write h or carry into buffer (m+1)%3, release flag m+1.
// Halting decisions are computed from identical global data in identical
// order in every block => uniform control flow across blocks.
__global__ void __launch_bounds__(256, 1) rnn_act(const float* __restrict__ W_hh,
                                                  const float* __restrict__ W_ih,
                                                  const float* __restrict__ W_halt,
                                                  const float* __restrict__ b_halt,
                                                  float* __restrict__ pond_out) {
    __shared__ __align__(16) u64   sh_W2[4096];    // [k=512][j=8] dup-pairs (32 KB)
    __shared__ __align__(16) u64   sh_part[1024];  // [grp=4][j=8][lane=32]    (8 KB)
    __shared__ float sh_hp[512];                   // halt partials [warp=8][b=64]
    __shared__ float sh_hn[512];                   // current h slice [j=8][b=64]
    __shared__ float sh_cum[64];
    __shared__ float sh_w[64];
    __shared__ float sh_pond[64];
    __shared__ int   sh_halted[64];
    __shared__ float sh_whalt[8];
    __shared__ float sh_wih0[8];
    __shared__ float sh_bhalt;

    const int blk  = blockIdx.x;
    const int tid  = threadIdx.x;
    const int warp = tid >> 5, lane = tid & 31;
    const int j = warp, b0 = lane * 2;             // thread <-> (j, b-pair) mapping

    // one-time: W_hh slice -> SMEM as duplicated f32x2 pairs, layout [k][j]
    for (int i = tid; i < 4096; i += 256) {
        int jj = i >> 9, k = i & 511;
        unsigned wb = __float_as_uint(W_hh[(blk * 8 + jj) * 512 + k]);
        sh_W2[k * 8 + jj] = ((u64)wb << 32) | (u64)wb;
    }
    if (tid < 8) {
        sh_whalt[tid] = W_halt[blk * 8 + tid];
        sh_wih0[tid]  = W_ih[(blk * 8 + tid) * 257];
    }
    if (tid == 0) sh_bhalt = b_halt[0];
    if (tid < 64) { sh_cum[tid] = 0.f; sh_pond[tid] = 0.f; sh_halted[tid] = 0; }
    __syncthreads();

    unsigned m = 0;               // global step counter (monotonic)
    int m3 = 0, nx3 = 1;          // m % 3, (m+1) % 3
    int t = 0, n = 0;             // timestep, local ponder index (uniform across blocks)
    float accx = 0.f, accy = 0.f; // acc_s for (j, b0/b0+1)
    float hpx = 0.f, hpy = 0.f;   // previous-step h for (j, b0/b0+1)

    const int fidx = (warp << 3) + (lane < 8 ? lane : 0);
    unsigned* myflag = &g_flag[fidx << 5];

    while (t < S_LEN) {
        // ---- phase 1: one vectorized readiness check for this warp's 8 producers ----
        for (;;) {
            unsigned v = (lane < 8) ? ld_acq(myflag) : 0xffffffffu;
            if (__all_sync(0xffffffffu, v >= m)) break;
            __nanosleep(32);
        }
        // ---- consume chunks + GEMM + halt-partial accumulate ----
        u64 q0=0,q1=0,q2=0,q3=0,q4=0,q5=0,q6=0,q7=0;
        float hpa = 0.f, hpb = 0.f;
        {
            const u64*   bufr = (const u64*)g_hbuf + m3 * 16384;
            const float* hvr  = g_haltv + m3 * 4096;
            #pragma unroll
            for (int c8 = 0; c8 < 8; ++c8) {
                const int pb = (warp << 3) + c8;
                const u64* rp = bufr + (pb << 8) + lane;
                #pragma unroll
                for (int kk = 0; kk < 8; ++kk) {
                    u64 h2 = __ldcg(rp + (kk << 5));
                    const ulonglong2* wr = (const ulonglong2*)(sh_W2 + (((pb << 3) + kk) << 3));
                    ulonglong2 w01 = wr[0], w23 = wr[1], w45 = wr[2], w67 = wr[3];
                    ffma2(q0, h2, w01.x); ffma2(q1, h2, w01.y);
                    ffma2(q2, h2, w23.x); ffma2(q3, h2, w23.y);
                    ffma2(q4, h2, w45.x); ffma2(q5, h2, w45.y);
                    ffma2(q6, h2, w67.x); ffma2(q7, h2, w67.y);
                }
                hpa += __ldcg(hvr + (pb << 6) + lane);
                hpb += __ldcg(hvr + (pb << 6) + 32 + lane);
            }
        }
        // ---- phase 2: stage K-partials (warps 0-3) + halt partials (all warps) ----
        if (warp < 4) {
            u64* pp = sh_part + (warp << 8) + lane;
            pp[0*32]=q0; pp[1*32]=q1; pp[2*32]=q2; pp[3*32]=q3;
            pp[4*32]=q4; pp[5*32]=q5; pp[6*32]=q6; pp[7*32]=q7;
        }
        sh_hp[(warp << 6) + lane]      = hpa;
        sh_hp[(warp << 6) + 32 + lane] = hpb;
        __syncthreads();
        // ---- phase 3: warps 4-7 fold; threads 0-63 finalize halting for q = n-1 ----
        if (warp >= 4) {
            u64* pp = sh_part + ((warp - 4) << 8) + lane;
            u64 v;
            v = pp[0*32]; pp[0*32] = pack2(lo32(v)+lo32(q0), hi32(v)+hi32(q0));
            v = pp[1*32]; pp[1*32] = pack2(lo32(v)+lo32(q1), hi32(v)+hi32(q1));
            v = pp[2*32]; pp[2*32] = pack2(lo32(v)+lo32(q2), hi32(v)+hi32(q2));
            v = pp[3*32]; pp[3*32] = pack2(lo32(v)+lo32(q3), hi32(v)+hi32(q3));
            v = pp[4*32]; pp[4*32] = pack2(lo32(v)+lo32(q4), hi32(v)+hi32(q4));
            v = pp[5*32]; pp[5*32] = pack2(lo32(v)+lo32(q5), hi32(v)+hi32(q5));
            v = pp[6*32]; pp[6*32] = pack2(lo32(v)+lo32(q6), hi32(v)+hi32(q6));
            v = pp[7*32]; pp[7*32] = pack2(lo32(v)+lo32(q7), hi32(v)+hi32(q7));
        }
        if (n >= 1 && tid < 64) {
            float s = 0.f;
            #pragma unroll
            for (int w8 = 0; w8 < 8; ++w8) s += sh_hp[(w8 << 6) + tid];   // fixed order
            float p = 1.f / (1.f + expf(-(s + sh_bhalt)));
            int hl = sh_halted[tid];
            if (hl) p = 0.f;
            float cum = sh_cum[tid];
            int is_h = (!hl) && (((cum + p) >= 0.99f) || (n - 1 == NMAX - 1));
            sh_w[tid] = is_h ? (1.f - cum) : p;
            if (is_h) sh_pond[tid] = (1.f - cum) + (float)n;   // (q+1) = n
            sh_cum[tid] = cum + p;
            sh_halted[tid] = hl | is_h;
        }
        int allh = __syncthreads_and((n == 0) ? 0 : (tid < 64 ? sh_halted[tid] : 1));
        // ---- phase 4: acc update (lagged), then write h_new or carry ----
        {
            if (n >= 1) { accx += sh_w[b0] * hpx; accy += sh_w[b0 + 1] * hpy; }
            const int gj = blk * 8 + j;
            u64* bw = (u64*)g_hbuf + nx3 * 16384 + (gj << 5) + lane;
            if (!allh) {
                float sx = 0.f, sy = 0.f;
                #pragma unroll
                for (int g = 0; g < 4; ++g) {
                    u64 v = sh_part[((g << 3) + j) * 32 + lane];
                    sx += lo32(v); sy += hi32(v);
                }
                const float2 pre2 = *(const float2*)(g_preT + ((t * 512 + gj) << 6) + b0);
                float ax = sx + pre2.x, ay = sy + pre2.y;
                if (n == 0) { float f = sh_wih0[j]; ax += f; ay += f; }
                float hx = tanhf(ax), hyv = tanhf(ay);
                hpx = hx; hpy = hyv;
                sh_hn[(j << 6) + b0]     = hx;
                sh_hn[(j << 6) + b0 + 1] = hyv;
                *bw = pack2(hx, hyv);
            } else {
                *bw = pack2(accx, accy);   // carry = acc_s -> next timestep's h input
                *(float2*)(g_accsT + ((t * 512 + gj) << 6) + b0) = make_float2(accx, accy);
            }
        }
        __syncthreads();
        // ---- phase 5: publish halt vector (or finish timestep) ----
        if (!allh) {
            if (tid < 64) {
                float s = 0.f;
                #pragma unroll
                for (int jj = 0; jj < 8; ++jj) s += sh_whalt[jj] * sh_hn[(jj << 6) + tid];
                g_haltv[nx3 * 4096 + (blk << 6) + tid] = s;
            }
            ++n;
        } else {
            if (blk == 0 && tid < 64) pond_out[t * 64 + tid] = sh_pond[tid];
            if (tid < 64) { sh_cum[tid] = 0.f; sh_pond[tid] = 0.f; sh_halted[tid] = 0; }
            accx = 0.f; accy = 0.f;
            ++t; n = 0;
        }
        __syncthreads();
        // ---- phase 6: release this block's flag for step m+1 ----
        if (tid == 0) st_rel(&g_flag[blk << 5], m + 1);
        ++m;
        m3 = nx3; nx3 = (nx3 + 1 == 3) ? 0 : nx3 + 1;
    }
}

// ---------------- kernel 3: output GEMM ----------------
__global__ void __launch_bounds__(256) out_gemm(const float* __restrict__ W_out,
                                                const float* __restrict__ b_out,
                                                float* __restrict__ out) {
    __shared__ float As[64 * 65];
    __shared__ float Ws[64 * 65];
    const int t = blockIdx.y, ot = blockIdx.x;
    const int tid = threadIdx.x;
    const int ty = tid >> 4, tx = tid & 15;
    float acc[4][4] = {};
    for (int kc = 0; kc < 8; ++kc) {
        __syncthreads();
        for (int i = tid; i < 4096; i += 256) {
            int r = i >> 6, c = i & 63;
            As[r * 65 + c] = g_accsT[(t * 512 + kc * 64 + r) * 64 + c];
            Ws[r * 65 + c] = W_out[(ot * 64 + r) * 512 + kc * 64 + c];
        }
        __syncthreads();
        #pragma unroll 8
        for (int kk = 0; kk < 64; ++kk) {
            float wv[4], xv[4];
            #pragma unroll
            for (int a = 0; a < 4; ++a) wv[a] = Ws[(ty * 4 + a) * 65 + kk];
            #pragma unroll
            for (int c = 0; c < 4; ++c) xv[c] = As[kk * 65 + tx * 4 + c];
            #pragma unroll
            for (int a = 0; a < 4; ++a)
                #pragma unroll
                for (int c = 0; c < 4; ++c)
                    acc[a][c] = fmaf(wv[a], xv[c], acc[a][c]);
        }
    }
    #pragma unroll
    for (int a = 0; a < 4; ++a) {
        int o = ot * 64 + ty * 4 + a;
        float bias = b_out[o];
        #pragma unroll
        for (int c = 0; c < 4; ++c) {
            int b = tx * 4 + c;
            out[(t * 64 + b) * 256 + o] = acc[a][c] + bias;
        }
    }
}

extern "C" void kernel_launch(void* const* d_in, const int* in_sizes, int n_in,
                              void* d_out, int out_size) {
    const float* x      = (const float*)d_in[0];
    const float* s      = (const float*)d_in[1];
    const float* W_ih   = (const float*)d_in[2];
    const float* b_ih   = (const float*)d_in[3];
    const float* W_hh   = (const float*)d_in[4];
    const float* b_hh   = (const float*)d_in[5];
    const float* W_out  = (const float*)d_in[6];
    const float* b_out  = (const float*)d_in[7];
    const float* W_halt = (const float*)d_in[8];
    const float* b_halt = (const float*)d_in[9];
    float* out  = (float*)d_out;                       // outputs [S,B,O]
    float* pond = out + S_LEN * B_SZ * O_SZ;           // ponder  [S,B]

    dim3 preg(8, S_LEN);
    pre_gemm<<<preg, 256>>>(x, W_ih, b_ih, b_hh);
    init_h<<<B_SZ, H_SZ>>>(s);
    rnn_act<<<NBLK, 256>>>(W_hh, W_ih, W_halt, b_halt, pond);
    dim3 outg(4, S_LEN);
    out_gemm<<<outg, 256>>>(W_out, b_out, out);
}